// round 10
// baseline (speedup 1.0000x reference)
#include <cuda_runtime.h>

// ECE loss: logits (8,19,512,1024) f32, labels (8,512,1024) int32 -> scalar f32.
//
// ECE = (1/total) * sum_bins | sum_{pixel in bin} (conf - correct) |
// conf = 1 / sum_c exp(x_c - max); correct = (argmax == label), first-max-wins.
//
// Single-kernel: fused streaming pass (float2, 2 px/thread), shared-mem bin
// accumulation -> 15 global float atomics per block; the LAST block (threadfence
// + atomic counter) folds the 15 bins into d_out[0] and resets state for the
// next graph replay. Launch period is 1, so ncu (-s 5 -c 1) must profile this.

#define NCLS   19
#define LOG_HW 19
#define HW     (1 << LOG_HW)          // 512*1024
#define NPIX   (8 * HW)               // 4194304
#define NPAIRS (NPIX / 2)
#define NTHR   256
#define NBLK   (NPAIRS / NTHR)        // 8192
#define NBINS  15

__device__ float        g_bins[NBINS];   // zero at load; last block resets
__device__ unsigned int g_count;         // zero at load; last block resets

__global__ void ece_main(const float* __restrict__ logits,
                         const int* __restrict__ labels,
                         float* __restrict__ out) {
    __shared__ float sS[NBINS];
    __shared__ bool  isLast;
    const int tid = threadIdx.x;
    if (tid < NBINS) sS[tid] = 0.0f;
    __syncthreads();

    const int t  = blockIdx.x * NTHR + tid;   // pixel-pair index
    const int p0 = t << 1;
    const int n  = p0 >> LOG_HW;
    const int q  = p0 & (HW - 1);
    const float* base = logits + (size_t)n * (NCLS * HW) + q;

    // 19 classes x 2 pixels: coalesced LDG.64 per class (256B/warp/class).
    float2 v[NCLS];
#pragma unroll
    for (int c = 0; c < NCLS; ++c)
        v[c] = *(const float2*)(base + c * HW);

    const int2 lab = ((const int2*)labels)[t];

    // Max + argmax (strict '>' == jnp.argmax first-max-wins).
    float m0 = v[0].x, m1 = v[0].y;
    int  ix0 = 0,      ix1 = 0;
#pragma unroll
    for (int c = 1; c < NCLS; ++c) {
        if (v[c].x > m0) { m0 = v[c].x; ix0 = c; }
        if (v[c].y > m1) { m1 = v[c].y; ix1 = c; }
    }

    // sum exp(x - m); conf = 1/s.
    float s0 = 0.0f, s1 = 0.0f;
#pragma unroll
    for (int c = 0; c < NCLS; ++c) {
        s0 += __expf(v[c].x - m0);
        s1 += __expf(v[c].y - m1);
    }
    const float conf0 = __fdividef(1.0f, s0);
    const float conf1 = __fdividef(1.0f, s1);

    const float val0 = conf0 - ((ix0 == lab.x) ? 1.0f : 0.0f);
    const float val1 = conf1 - ((ix1 == lab.y) ? 1.0f : 0.0f);

    // bin = clamp(ceil(conf*15)-1, 0, 14) == searchsorted(left)-1
    int b0 = __float2int_ru(conf0 * 15.0f) - 1;
    int b1 = __float2int_ru(conf1 * 15.0f) - 1;
    b0 = min(max(b0, 0), NBINS - 1);
    b1 = min(max(b1, 0), NBINS - 1);

    atomicAdd(&sS[b0], val0);
    atomicAdd(&sS[b1], val1);
    __syncthreads();

    if (tid < NBINS)
        atomicAdd(&g_bins[tid], sS[tid]);

    // Last-block finish (threadfence-reduction pattern).
    if (tid == 0) {
        __threadfence();
        isLast = (atomicAdd(&g_count, 1u) == NBLK - 1);
    }
    __syncthreads();

    if (isLast && tid < 32) {
        // L2 read (bins were written by global atomics -> live in L2).
        float x = (tid < NBINS) ? __ldcg(&g_bins[tid]) : 0.0f;
        float e = fabsf(x);
#pragma unroll
        for (int o = 16; o > 0; o >>= 1)
            e += __shfl_down_sync(0xffffffffu, e, o);
        if (tid == 0) {
            out[0] = e * (1.0f / (float)NPIX);
            g_count = 0;                   // reset for next graph replay
        }
        if (tid < NBINS)
            g_bins[tid] = 0.0f;
    }
}

extern "C" void kernel_launch(void* const* d_in, const int* in_sizes, int n_in,
                              void* d_out, int out_size) {
    const float* logits = (const float*)d_in[0];
    const int*   labels = (const int*)d_in[1];
    float*       out    = (float*)d_out;

    ece_main<<<NBLK, NTHR>>>(logits, labels, out);
}

// round 16
// speedup vs baseline: 1.7626x; 1.7626x over previous
#include <cuda_runtime.h>

// ECE loss: logits (8,19,512,1024) f32, labels (8,512,1024) int32 -> scalar f32.
//
// ECE = (1/total) * sum_bins | sum_{pixel in bin} (conf - correct) |
// conf = 1 / sum_c exp(x_c - max); correct = (argmax == label), first-max-wins.
//
// R11: online softmax (1 expf/element, no v[] register array) -> float4,
// 4 px/thread without spills; 8x-replicated shared bins (conflict 32 -> 4);
// last-block fold with per-writer threadfence.

#define NCLS    19
#define LOG_HW  19
#define HW      (1 << LOG_HW)          // 512*1024
#define NPIX    (8 * HW)               // 4194304
#define PXTHR   4
#define NTHR    256
#define NBLK    (NPIX / PXTHR / NTHR)  // 4096
#define NBINS   15
#define REP     8
#define RSTRIDE 17                     // banks of replicas all distinct

__device__ float        g_bins[NBINS];  // zero at load; last block resets
__device__ unsigned int g_count;        // zero at load; last block resets

__global__ void __launch_bounds__(NTHR)
ece_main(const float* __restrict__ logits,
         const int* __restrict__ labels,
         float* __restrict__ out) {
    __shared__ float sS[REP * RSTRIDE];
    __shared__ bool  isLast;
    const int tid = threadIdx.x;
    for (int i = tid; i < REP * RSTRIDE; i += NTHR) sS[i] = 0.0f;
    __syncthreads();

    const int t  = blockIdx.x * NTHR + tid;   // quad index
    const int p0 = t << 2;                    // 4 consecutive pixels
    const int n  = p0 >> LOG_HW;
    const int q  = p0 & (HW - 1);
    const float* base = logits + (size_t)n * (NCLS * HW) + q;

    // Online softmax over classes: state (m, s, ix) per pixel; one LDG.128
    // per class (512B/warp), one expf per element.
    const float4 x0 = *(const float4*)base;
    float m[4] = {x0.x, x0.y, x0.z, x0.w};
    float s[4] = {1.0f, 1.0f, 1.0f, 1.0f};    // exp(x0 - m) = 1
    int  ix[4] = {0, 0, 0, 0};

#pragma unroll
    for (int c = 1; c < NCLS; ++c) {
        const float4 xc = *(const float4*)(base + c * HW);
        const float w[4] = {xc.x, xc.y, xc.z, xc.w};
#pragma unroll
        for (int k = 0; k < 4; ++k) {
            const float mo = m[k];
            const bool  p  = (w[k] > mo);
            const float ed = __expf(-fabsf(w[k] - mo));   // exp(min - max)
            // p: s*ed + 1 (new max);  !p: s + ed
            s[k]  = fmaf(s[k], p ? ed : 1.0f, p ? 1.0f : ed);
            m[k]  = p ? w[k] : mo;
            ix[k] = p ? c : ix[k];
        }
    }

    const int4 lab = ((const int4*)labels)[t];
    const int lb[4] = {lab.x, lab.y, lab.z, lab.w};
    const int rep = tid & (REP - 1);

#pragma unroll
    for (int k = 0; k < 4; ++k) {
        const float conf = __fdividef(1.0f, s[k]);
        const float val  = conf - ((ix[k] == lb[k]) ? 1.0f : 0.0f);
        // bin = clamp(ceil(conf*15)-1, 0, 14) == searchsorted(left)-1
        int b = __float2int_ru(conf * 15.0f) - 1;
        b = min(max(b, 0), NBINS - 1);
        atomicAdd(&sS[rep * RSTRIDE + b], val);
    }
    __syncthreads();

    // Fold replicas -> 15 global atomics per block, fence by the writers.
    if (tid < NBINS) {
        float acc = 0.0f;
#pragma unroll
        for (int r = 0; r < REP; ++r) acc += sS[r * RSTRIDE + tid];
        atomicAdd(&g_bins[tid], acc);
        __threadfence();
    }
    __syncthreads();

    if (tid == 0)
        isLast = (atomicAdd(&g_count, 1u) == NBLK - 1);
    __syncthreads();

    if (isLast && tid < 32) {
        float x = (tid < NBINS) ? __ldcg(&g_bins[tid]) : 0.0f;
        float e = fabsf(x);
#pragma unroll
        for (int o = 16; o > 0; o >>= 1)
            e += __shfl_down_sync(0xffffffffu, e, o);
        if (tid == 0) {
            out[0] = e * (1.0f / (float)NPIX);
            g_count = 0;                   // reset for next graph replay
        }
        if (tid < NBINS)
            g_bins[tid] = 0.0f;            // reset for next graph replay
    }
}

extern "C" void kernel_launch(void* const* d_in, const int* in_sizes, int n_in,
                              void* d_out, int out_size) {
    const float* logits = (const float*)d_in[0];
    const int*   labels = (const int*)d_in[1];
    float*       out    = (float*)d_out;

    ece_main<<<NBLK, NTHR>>>(logits, labels, out);
}